// round 9
// baseline (speedup 1.0000x reference)
#include <cuda_runtime.h>
#include <math.h>

#define NB 16
#define NT 32
#define HH 40
#define WW 40
#define FF 40
#define GATES 160   // 4*FF

typedef unsigned long long ull;

// ---------------- scratch (no allocations allowed) ----------------
__device__ float g_seqA[(size_t)NB*NT*HH*WW*FF];   // 131 MB
__device__ float g_seqB[(size_t)NB*NT*HH*WW*FF];   // 131 MB
__device__ float g_hA[NB*HH*WW*FF];
__device__ float g_hB[NB*HH*WW*FF];
__device__ float g_c [NB*HH*WW*FF];

__global__ void zero_kernel(float* __restrict__ p, int n) {
    int i = blockIdx.x * blockDim.x + threadIdx.x;
    if (i < n) p[i] = 0.f;
}

__device__ __forceinline__ float hsig(float x) {
    return fminf(fmaxf(0.2f * x + 0.5f, 0.f), 1.f);
}
__device__ __forceinline__ ull pack2(float v) {
    ull r; asm("mov.b64 %0, {%1, %1};" : "=l"(r) : "f"(v)); return r;
}
__device__ __forceinline__ void ffma2(ull& d, ull a, ull b) {
    asm("fma.rn.f32x2 %0, %1, %2, %0;" : "+l"(d) : "l"(a), "l"(b));
}
__device__ __forceinline__ float2 unpk(ull v) {
    float lo, hi; asm("mov.b64 {%0, %1}, %2;" : "=f"(lo), "=f"(hi) : "l"(v));
    return make_float2(lo, hi);
}

// ---------------- fused ConvLSTM step + BN epilogue ----------------
// Block: one (batch b, output row): 40 pixels x 160 gate channels.
// blockDim = (20, 10). Thread (tx, ty): pixels w=tx and w=tx+20,
// f-channels jb..jb+3 (jb=ty*4) for all 4 gates.
// Accumulators are f32x2 pairs: A[p][0..7] = {i01,i23,f01,f23,g01,g23,o01,o23}.
template <int CIN>
__global__ __launch_bounds__(200)
void lstm_step_kernel(
    const float* __restrict__ x_t, int bstride_x,     // x_t + b*bstride_x -> [H][W][CIN]
    const float* __restrict__ h_prev,                 // [B][H][W][FF]
    float*       __restrict__ h_next,                 // [B][H][W][FF]
    float*       __restrict__ c_buf,                  // [B][H][W][FF]
    float*       __restrict__ out_t, int bstride_o,   // out_t + b*bstride_o -> [H][W][FF]
    const float* __restrict__ Wx,                     // [3][3][CIN][160]
    const float* __restrict__ Wh,                     // [3][3][FF][160]
    const float* __restrict__ bias,                   // [160]
    const float* __restrict__ gam,
    const float* __restrict__ bet,
    const float* __restrict__ mu,
    const float* __restrict__ var)
{
    // [c][j] with j = dy*42 + col (col = w+1 halo), row stride padded to 127
    __shared__ __align__(16) float xs[CIN * 127];
    __shared__ __align__(16) float hs[FF  * 127];

    const int tx  = threadIdx.x;   // 0..19
    const int ty  = threadIdx.y;   // 0..9
    const int row = blockIdx.x;    // 0..39
    const int b   = blockIdx.y;    // 0..15
    const int tid = ty * 20 + tx;

    const float* xb = x_t    + (size_t)b * bstride_x;
    const float* hb = h_prev + (size_t)b * (HH * WW * FF);

    // tile loads: c fastest for coalescing; smem write stride 127 (conflict-free)
    for (int i = tid; i < CIN * 126; i += 200) {
        int c = i % CIN, j = i / CIN;
        int dy = j / 42, col = j % 42;
        int rr = row + dy - 1, cc = col - 1;
        float v = 0.f;
        if ((unsigned)rr < HH && (unsigned)cc < WW) v = xb[(rr * WW + cc) * CIN + c];
        xs[c * 127 + j] = v;
    }
    for (int i = tid; i < FF * 126; i += 200) {
        int c = i % FF, j = i / FF;
        int dy = j / 42, col = j % 42;
        int rr = row + dy - 1, cc = col - 1;
        float v = 0.f;
        if ((unsigned)rr < HH && (unsigned)cc < WW) v = hb[(rr * WW + cc) * FF + c];
        hs[c * 127 + j] = v;
    }
    __syncthreads();

    const int jb = ty * 4;
    ull A[2][8];
    {
        ulonglong2 bi = *(const ulonglong2*)(bias + 0 * FF + jb);
        ulonglong2 bf = *(const ulonglong2*)(bias + 1 * FF + jb);
        ulonglong2 bg = *(const ulonglong2*)(bias + 2 * FF + jb);
        ulonglong2 bo = *(const ulonglong2*)(bias + 3 * FF + jb);
        A[0][0] = A[1][0] = bi.x;  A[0][1] = A[1][1] = bi.y;
        A[0][2] = A[1][2] = bf.x;  A[0][3] = A[1][3] = bf.y;
        A[0][4] = A[1][4] = bg.x;  A[0][5] = A[1][5] = bg.y;
        A[0][6] = A[1][6] = bo.x;  A[0][7] = A[1][7] = bo.y;
    }

#define STEP16(P, V, WI, WF, WG, WO)            \
    ffma2(A[P][0], V, (WI).x); ffma2(A[P][1], V, (WI).y); \
    ffma2(A[P][2], V, (WF).x); ffma2(A[P][3], V, (WF).y); \
    ffma2(A[P][4], V, (WG).x); ffma2(A[P][5], V, (WG).y); \
    ffma2(A[P][6], V, (WO).x); ffma2(A[P][7], V, (WO).y);

#pragma unroll 1
    for (int dy = 0; dy < 3; dy++) {
#pragma unroll 1
        for (int dw = 0; dw < 3; dw++) {
            const int k = dy * 3 + dw;
            {   // x-conv contribution
                const float* wk = Wx + (size_t)k * CIN * GATES + jb;
                const float* p0 = xs + dy * 42 + tx + dw;
                const float* p1 = p0 + 20;
#pragma unroll 4
                for (int c = 0; c < CIN; c++) {
                    const float* wc = wk + c * GATES;
                    ulonglong2 wi = *(const ulonglong2*)(wc);
                    ulonglong2 wf = *(const ulonglong2*)(wc + FF);
                    ulonglong2 wg = *(const ulonglong2*)(wc + 2 * FF);
                    ulonglong2 wo = *(const ulonglong2*)(wc + 3 * FF);
                    ull v0 = pack2(p0[c * 127]);
                    ull v1 = pack2(p1[c * 127]);
                    STEP16(0, v0, wi, wf, wg, wo)
                    STEP16(1, v1, wi, wf, wg, wo)
                }
            }
            {   // h-conv contribution
                const float* wk = Wh + (size_t)k * FF * GATES + jb;
                const float* p0 = hs + dy * 42 + tx + dw;
                const float* p1 = p0 + 20;
#pragma unroll 4
                for (int c = 0; c < FF; c++) {
                    const float* wc = wk + c * GATES;
                    ulonglong2 wi = *(const ulonglong2*)(wc);
                    ulonglong2 wf = *(const ulonglong2*)(wc + FF);
                    ulonglong2 wg = *(const ulonglong2*)(wc + 2 * FF);
                    ulonglong2 wo = *(const ulonglong2*)(wc + 3 * FF);
                    ull v0 = pack2(p0[c * 127]);
                    ull v1 = pack2(p1[c * 127]);
                    STEP16(0, v0, wi, wf, wg, wo)
                    STEP16(1, v1, wi, wf, wg, wo)
                }
            }
        }
    }
#undef STEP16

    // ---- epilogue: cell update + BN, for both pixels ----
    const int pixrow = (b * HH + row) * WW;
#pragma unroll
    for (int p = 0; p < 2; p++) {
        const int w = tx + 20 * p;
        const int pix = pixrow + w;
        float z[16];
#pragma unroll
        for (int q = 0; q < 8; q++) {
            float2 t = unpk(A[p][q]);
            z[q * 2] = t.x; z[q * 2 + 1] = t.y;
        }
        // z[0..3]=i, z[4..7]=f, z[8..11]=g, z[12..15]=o  (channels jb..jb+3)
        float4* cp = (float4*)(c_buf + (size_t)pix * FF + jb);
        float4 cv = *cp;
        float cc4[4] = {cv.x, cv.y, cv.z, cv.w};
        float hh4[4], oo4[4];
#pragma unroll
        for (int q = 0; q < 4; q++) {
            float cn = hsig(z[4 + q]) * cc4[q] + hsig(z[q]) * tanhf(z[8 + q]);
            cc4[q] = cn;
            float h = hsig(z[12 + q]) * tanhf(cn);
            hh4[q] = h;
            int f = jb + q;
            float sc = gam[f] * rsqrtf(var[f] + 1e-3f);
            oo4[q] = (h - mu[f]) * sc + bet[f];
        }
        float4 cn4 = make_float4(cc4[0], cc4[1], cc4[2], cc4[3]);
        float4 hn4 = make_float4(hh4[0], hh4[1], hh4[2], hh4[3]);
        float4 ob4 = make_float4(oo4[0], oo4[1], oo4[2], oo4[3]);
        *cp = cn4;
        *(float4*)(h_next + (size_t)pix * FF + jb) = hn4;
        *(float4*)(out_t + (size_t)b * bstride_o + (size_t)(row * WW + w) * FF + jb) = ob4;
    }
}

// ---------------- final Conv3D (3x3x3 over T,H,W) + sigmoid ----------------
__global__ __launch_bounds__(320)
void conv3d_kernel(const float* __restrict__ in,    // [B][T][H][W][FF]
                   const float* __restrict__ W3,    // [3][3][3][FF]
                   const float* __restrict__ b3,
                   float* __restrict__ out)         // [B][T][H][W]
{
    __shared__ __align__(16) float ws[27 * FF];
    int tid = threadIdx.y * 40 + threadIdx.x;
    for (int i = tid; i < 27 * FF; i += 320) ws[i] = W3[i];
    __syncthreads();

    const int w   = threadIdx.x;
    const int t   = blockIdx.x * 8 + threadIdx.y;
    const int row = blockIdx.y;
    const int b   = blockIdx.z;

    float acc = b3[0];
#pragma unroll
    for (int dt = 0; dt < 3; dt++) {
        int tt = t + dt - 1;
        if ((unsigned)tt >= NT) continue;
#pragma unroll
        for (int dh = 0; dh < 3; dh++) {
            int rr = row + dh - 1;
            if ((unsigned)rr >= HH) continue;
            const float* rp = in + ((size_t)(b * NT + tt) * HH + rr) * WW * FF;
#pragma unroll
            for (int dw = 0; dw < 3; dw++) {
                int cc = w + dw - 1;
                if ((unsigned)cc >= WW) continue;
                const float4* pp = (const float4*)(rp + (size_t)cc * FF);
                const float*  wp = ws + ((dt * 3 + dh) * 3 + dw) * FF;
#pragma unroll
                for (int q = 0; q < 10; q++) {
                    float4 v  = pp[q];
                    float4 wv = *(const float4*)(wp + q * 4);
                    acc += v.x * wv.x + v.y * wv.y + v.z * wv.z + v.w * wv.w;
                }
            }
        }
    }
    out[((size_t)(b * NT + t) * HH + row) * WW + w] = 1.f / (1.f + expf(-acc));
}

// ---------------- launch ----------------
extern "C" void kernel_launch(void* const* d_in, const int* in_sizes, int n_in,
                              void* d_out, int out_size)
{
    (void)in_sizes; (void)n_in; (void)out_size;
    const float* inputs = (const float*)d_in[0];

    struct LayerP { const float *Wx, *Wh, *b, *g, *be, *mu, *v; };
    LayerP L[4];
    for (int l = 0; l < 4; l++) {
        int base = 1 + 7 * l;
        L[l].Wx = (const float*)d_in[base + 0];
        L[l].Wh = (const float*)d_in[base + 1];
        L[l].b  = (const float*)d_in[base + 2];
        L[l].g  = (const float*)d_in[base + 3];
        L[l].be = (const float*)d_in[base + 4];
        L[l].mu = (const float*)d_in[base + 5];
        L[l].v  = (const float*)d_in[base + 6];
    }
    const float* W3 = (const float*)d_in[29];
    const float* b3 = (const float*)d_in[30];

    float *seqA, *seqB, *hA, *hB, *cbuf;
    cudaGetSymbolAddress((void**)&seqA, g_seqA);
    cudaGetSymbolAddress((void**)&seqB, g_seqB);
    cudaGetSymbolAddress((void**)&hA,   g_hA);
    cudaGetSymbolAddress((void**)&hB,   g_hB);
    cudaGetSymbolAddress((void**)&cbuf, g_c);

    const dim3 blk(20, 10), grd(HH, NB);
    const int nhc = NB * HH * WW * FF;

    const float* in_base = inputs;
    int cin = 1;
    float* out_base = seqA;

    for (int l = 0; l < 4; l++) {
        zero_kernel<<<(nhc + 255) / 256, 256>>>(hA, nhc);
        zero_kernel<<<(nhc + 255) / 256, 256>>>(cbuf, nhc);
        float* hc = hA;
        float* hn = hB;
        const int bsx = NT * HH * WW * cin;
        const int bso = NT * HH * WW * FF;
        for (int t = 0; t < NT; t++) {
            const float* xt = in_base + (size_t)t * HH * WW * cin;
            float* ot = out_base + (size_t)t * HH * WW * FF;
            if (cin == 1) {
                lstm_step_kernel<1><<<grd, blk>>>(xt, bsx, hc, hn, cbuf, ot, bso,
                                                  L[l].Wx, L[l].Wh, L[l].b,
                                                  L[l].g, L[l].be, L[l].mu, L[l].v);
            } else {
                lstm_step_kernel<40><<<grd, blk>>>(xt, bsx, hc, hn, cbuf, ot, bso,
                                                   L[l].Wx, L[l].Wh, L[l].b,
                                                   L[l].g, L[l].be, L[l].mu, L[l].v);
            }
            float* tmp = hc; hc = hn; hn = tmp;
        }
        in_base = out_base;
        cin = FF;
        out_base = (out_base == seqA) ? seqB : seqA;
    }

    conv3d_kernel<<<dim3(4, HH, NB), dim3(40, 8)>>>(in_base, W3, b3, (float*)d_out);
}

// round 13
// speedup vs baseline: 1.8172x; 1.8172x over previous
#include <cuda_runtime.h>
#include <math.h>
#include <stdint.h>

#define NB 16
#define NT 32
#define HH 40
#define WW 40
#define FF 40

// ---------------- scratch (no allocations allowed) ----------------
__device__ float g_seqA[(size_t)NB*NT*HH*WW*FF];   // 131 MB
__device__ float g_seqB[(size_t)NB*NT*HH*WW*FF];   // 131 MB
__device__ float g_zx [(size_t)NB*NT*HH*WW*160];   // 524 MB  x-conv precompute
__device__ float g_hA[NB*HH*WW*FF];
__device__ float g_hB[NB*HH*WW*FF];
__device__ float g_c [NB*HH*WW*FF];
__device__ float g_Bxh[160*384], g_Bxl[160*384];   // x-weights packed hi/lo
__device__ float g_Bhh[160*384], g_Bhl[160*384];   // h-weights packed hi/lo

__global__ void zero_kernel(float* __restrict__ p, int n) {
    int i = blockIdx.x * blockDim.x + threadIdx.x;
    if (i < n) p[i] = 0.f;
}

__device__ __forceinline__ float hsig(float x) {
    return fminf(fmaxf(0.2f * x + 0.5f, 0.f), 1.f);
}
__device__ __forceinline__ float tf32r(float x) {
    uint32_t r; asm("cvt.rna.tf32.f32 %0, %1;" : "=r"(r) : "f"(x));
    return __uint_as_float(r);
}
// m16n8k8 tf32 mma: d += a * b  (a: 4 regs, b: 2 regs, d: 4 f32)
__device__ __forceinline__ void mma8(float* d, const uint32_t* a, uint32_t b0, uint32_t b1) {
    asm volatile("mma.sync.aligned.m16n8k8.row.col.f32.tf32.tf32.f32 "
        "{%0,%1,%2,%3}, {%4,%5,%6,%7}, {%8,%9}, {%0,%1,%2,%3};"
        : "+f"(d[0]), "+f"(d[1]), "+f"(d[2]), "+f"(d[3])
        : "r"(a[0]), "r"(a[1]), "r"(a[2]), "r"(a[3]), "r"(b0), "r"(b1));
}

// ---- weight prepass ----
// mode 0 (CIN=1):  out[n][k16]   : k<9 -> W[k*160+n], else 0          (160*16)
// mode 1 (CIN=40): out[c][n][j40]: W[(c*40+j)*160+n], c=0..8          (9*160*40)
__global__ void build_B_kernel(const float* __restrict__ W, int mode,
                               float* __restrict__ Bh, float* __restrict__ Bl)
{
    int idx = blockIdx.x * blockDim.x + threadIdx.x;
    float v = 0.f;
    if (mode == 0) {
        if (idx >= 160 * 16) return;
        int n = idx / 16, k = idx & 15;
        if (k < 9) v = W[k * 160 + n];
    } else {
        if (idx >= 9 * 160 * 40) return;
        int c = idx / 6400, r = idx - c * 6400;
        int n = r / 40, j = r - n * 40;
        v = W[(size_t)(c * 40 + j) * 160 + n];
    }
    float hi = tf32r(v);
    Bh[idx] = hi;
    Bl[idx] = tf32r(v - hi);
}

// ---------------- GEMM step via mma.sync (tf32 3-term split) ----------------
// z[M,160] = im2col(X)[M, K=9*CIN] @ B[160,K]^T
// CTA: 128 threads, 4 warps; warp tile m16 x n160 (20 n-frags, all gates local).
// PRE=1: write z to zpre[p*160].  PRE=0: fused LSTM + BN epilogue.
template<int CIN, int PRE>
__global__ __launch_bounds__(128)
void mma_step(const float* __restrict__ X, long long xbs,
              const float* __restrict__ Bh_g, const float* __restrict__ Bl_g,
              float* __restrict__ zpre,
              const float* __restrict__ zx_t, long long zbs,
              const float* __restrict__ bias,
              const float* __restrict__ gam, const float* __restrict__ bet,
              const float* __restrict__ mu, const float* __restrict__ var,
              float* __restrict__ h_next, float* __restrict__ c_buf,
              float* __restrict__ out_t, long long bso)
{
    constexpr int CHUNKS  = (CIN == 1) ? 1 : 9;
    constexpr int CHUNK_K = (CIN == 1) ? 16 : 40;
    constexpr int AS      = (CIN == 1) ? 20 : 44;   // padded row stride (floats)
    constexpr int KSTEPS  = (CIN == 1) ? 2 : 5;

    extern __shared__ float smem[];
    float* sAh = smem;
    float* sAl = sAh + 64 * AS;
    float* sBh = sAl + 64 * AS;
    float* sBl = sBh + 160 * AS;
    float* sPar = sBl + 160 * AS;   // REC: bias[160], scale[40], shift[40]

    const int tid = threadIdx.x;
    const int w   = tid >> 5;
    const int lane = tid & 31;
    const int gid = lane >> 2;      // group id 0..7
    const int tig = lane & 3;       // thread-in-group 0..3
    const int p0  = blockIdx.x * 64;

    if (!PRE) {
        for (int i = tid; i < 240; i += 128) {
            if (i < 160) sPar[i] = bias[i];
            else if (i < 200) {
                int f = i - 160;
                sPar[i] = gam[f] * rsqrtf(var[f] + 1e-3f);
            } else {
                int f = i - 200;
                sPar[i] = bet[f] - mu[f] * (gam[f] * rsqrtf(var[f] + 1e-3f));
            }
        }
    }

    float d[20][4];
#pragma unroll
    for (int j = 0; j < 20; j++)
#pragma unroll
        for (int e = 0; e < 4; e++) d[j][e] = 0.f;

#pragma unroll 1
    for (int c = 0; c < CHUNKS; c++) {
        // ---- stage A: 64 rows x CHUNK_K (im2col gather + tf32 hi/lo split)
        if (CIN == 1) {
            for (int i = tid; i < 64 * 4; i += 128) {
                int row = i >> 2, g = i & 3;
                int p = p0 + row;
                int unit = p / 1600, pp = p - unit * 1600;
                int pr = pp / 40, pw = pp - pr * 40;
                float vv[4];
#pragma unroll
                for (int s = 0; s < 4; s++) {
                    int k = g * 4 + s;
                    float v = 0.f;
                    if (k < 9) {
                        int rr = pr + k / 3 - 1, cc = pw + k % 3 - 1;
                        if ((unsigned)rr < 40u && (unsigned)cc < 40u)
                            v = X[(size_t)unit * xbs + rr * 40 + cc];
                    }
                    vv[s] = v;
                }
#pragma unroll
                for (int s = 0; s < 4; s++) {
                    float hi = tf32r(vv[s]);
                    sAh[row * AS + g * 4 + s] = hi;
                    sAl[row * AS + g * 4 + s] = tf32r(vv[s] - hi);
                }
            }
            for (int i = tid; i < 160 * 4; i += 128) {
                int n = i >> 2, g = i & 3;
                float4 vh = *(const float4*)(Bh_g + n * 16 + g * 4);
                float4 vl = *(const float4*)(Bl_g + n * 16 + g * 4);
                *(float4*)(sBh + n * AS + g * 4) = vh;
                *(float4*)(sBl + n * AS + g * 4) = vl;
            }
        } else {
            const int dyy = c / 3 - 1, dxx = c % 3 - 1;
            for (int i = tid; i < 64 * 10; i += 128) {
                int row = i / 10, g = i - row * 10;
                int p = p0 + row;
                int unit = p / 1600, pp = p - unit * 1600;
                int pr = pp / 40, pw = pp - pr * 40;
                int rr = pr + dyy, cc = pw + dxx;
                float4 v = make_float4(0.f, 0.f, 0.f, 0.f);
                if ((unsigned)rr < 40u && (unsigned)cc < 40u)
                    v = *(const float4*)(X + (size_t)unit * xbs
                                         + (size_t)(rr * 40 + cc) * 40 + g * 4);
                float4 hi, lo;
                hi.x = tf32r(v.x); lo.x = tf32r(v.x - hi.x);
                hi.y = tf32r(v.y); lo.y = tf32r(v.y - hi.y);
                hi.z = tf32r(v.z); lo.z = tf32r(v.z - hi.z);
                hi.w = tf32r(v.w); lo.w = tf32r(v.w - hi.w);
                *(float4*)(sAh + row * AS + g * 4) = hi;
                *(float4*)(sAl + row * AS + g * 4) = lo;
            }
            for (int i = tid; i < 160 * 10; i += 128) {
                int n = i / 10, g = i - n * 10;
                size_t src = (size_t)(c * 160 + n) * 40 + g * 4;
                float4 vh = *(const float4*)(Bh_g + src);
                float4 vl = *(const float4*)(Bl_g + src);
                *(float4*)(sBh + n * AS + g * 4) = vh;
                *(float4*)(sBl + n * AS + g * 4) = vl;
            }
        }
        __syncthreads();

        // ---- mma over this chunk
        const uint32_t* Ah32 = (const uint32_t*)sAh;
        const uint32_t* Al32 = (const uint32_t*)sAl;
        const uint32_t* Bh32 = (const uint32_t*)sBh;
        const uint32_t* Bl32 = (const uint32_t*)sBl;
#pragma unroll
        for (int ks = 0; ks < KSTEPS; ks++) {
            const int kk = ks * 8;
            uint32_t ah[4], al[4];
            {
                int ra = (w * 16 + gid) * AS + kk + tig;
                ah[0] = Ah32[ra];          ah[1] = Ah32[ra + 8 * AS];
                ah[2] = Ah32[ra + 4];      ah[3] = Ah32[ra + 8 * AS + 4];
                al[0] = Al32[ra];          al[1] = Al32[ra + 8 * AS];
                al[2] = Al32[ra + 4];      al[3] = Al32[ra + 8 * AS + 4];
            }
#pragma unroll
            for (int j = 0; j < 20; j++) {
                int rb = (8 * j + gid) * AS + kk + tig;
                uint32_t bh0 = Bh32[rb], bh1 = Bh32[rb + 4];
                uint32_t bl0 = Bl32[rb], bl1 = Bl32[rb + 4];
                mma8(d[j], ah, bh0, bh1);
                mma8(d[j], ah, bl0, bl1);
                mma8(d[j], al, bh0, bh1);
            }
        }
        __syncthreads();
    }

    // ---------------- epilogue ----------------
    // Thread holds rows (w*16+gid, +8), cols {8j'+2tig, +1} in each gate block.
#pragma unroll
    for (int half = 0; half < 2; half++) {
        const int r = w * 16 + gid + 8 * half;
        const int p = p0 + r;
        if (PRE) {
            float* zp = zpre + (size_t)p * 160;
#pragma unroll
            for (int g = 0; g < 4; g++)
#pragma unroll
                for (int j = 0; j < 5; j++) {
                    int n = g * 40 + 8 * j + 2 * tig;
                    float2 v = make_float2(d[g * 5 + j][half * 2],
                                           d[g * 5 + j][half * 2 + 1]);
                    *(float2*)(zp + n) = v;
                }
        } else {
            const int b = p / 1600, pp = p - b * 1600;
            const float* zr = zx_t + (size_t)b * zbs + (size_t)pp * 160;
            float* cb = c_buf  + (size_t)p * 40;
            float* hb = h_next + (size_t)p * 40;
            float* ob = out_t  + (size_t)b * bso + (size_t)pp * 40;
#pragma unroll
            for (int j = 0; j < 5; j++) {
                const int ch = 8 * j + 2 * tig;
                float2 xi = *(const float2*)(zr + ch);
                float2 xf = *(const float2*)(zr + 40 + ch);
                float2 xg = *(const float2*)(zr + 80 + ch);
                float2 xo = *(const float2*)(zr + 120 + ch);
                float2 cc = *(const float2*)(cb + ch);
                float2 cn, hn, on;
#pragma unroll
                for (int e = 0; e < 2; e++) {
                    int n = ch + e;
                    int di = half * 2 + e;
                    float zi = (e ? xi.y : xi.x) + d[0 * 5 + j][di] + sPar[n];
                    float zf = (e ? xf.y : xf.x) + d[1 * 5 + j][di] + sPar[40 + n];
                    float zg = (e ? xg.y : xg.x) + d[2 * 5 + j][di] + sPar[80 + n];
                    float zo = (e ? xo.y : xo.x) + d[3 * 5 + j][di] + sPar[120 + n];
                    float cold = e ? cc.y : cc.x;
                    float cq = hsig(zf) * cold + hsig(zi) * tanhf(zg);
                    float hq = hsig(zo) * tanhf(cq);
                    float oq = hq * sPar[160 + n] + sPar[200 + n];
                    if (e) { cn.y = cq; hn.y = hq; on.y = oq; }
                    else   { cn.x = cq; hn.x = hq; on.x = oq; }
                }
                *(float2*)(cb + ch) = cn;
                *(float2*)(hb + ch) = hn;
                *(float2*)(ob + ch) = on;
            }
        }
    }
}

// ---------------- final Conv3D (3x3x3 over T,H,W) + sigmoid ----------------
__global__ __launch_bounds__(320)
void conv3d_kernel(const float* __restrict__ in,    // [B][T][H][W][FF]
                   const float* __restrict__ W3,    // [3][3][3][FF]
                   const float* __restrict__ b3,
                   float* __restrict__ out)         // [B][T][H][W]
{
    __shared__ __align__(16) float ws[27 * FF];
    int tid = threadIdx.y * 40 + threadIdx.x;
    for (int i = tid; i < 27 * FF; i += 320) ws[i] = W3[i];
    __syncthreads();

    const int w   = threadIdx.x;
    const int t   = blockIdx.x * 8 + threadIdx.y;
    const int row = blockIdx.y;
    const int b   = blockIdx.z;

    float acc = b3[0];
#pragma unroll
    for (int dt = 0; dt < 3; dt++) {
        int tt = t + dt - 1;
        if ((unsigned)tt >= NT) continue;
#pragma unroll
        for (int dh = 0; dh < 3; dh++) {
            int rr = row + dh - 1;
            if ((unsigned)rr >= HH) continue;
            const float* rp = in + ((size_t)(b * NT + tt) * HH + rr) * WW * FF;
#pragma unroll
            for (int dw = 0; dw < 3; dw++) {
                int cc = w + dw - 1;
                if ((unsigned)cc >= WW) continue;
                const float4* pp = (const float4*)(rp + (size_t)cc * FF);
                const float*  wp = ws + ((dt * 3 + dh) * 3 + dw) * FF;
#pragma unroll
                for (int q = 0; q < 10; q++) {
                    float4 v  = pp[q];
                    float4 wv = *(const float4*)(wp + q * 4);
                    acc += v.x * wv.x + v.y * wv.y + v.z * wv.z + v.w * wv.w;
                }
            }
        }
    }
    out[((size_t)(b * NT + t) * HH + row) * WW + w] = 1.f / (1.f + expf(-acc));
}

// ---------------- launch ----------------
extern "C" void kernel_launch(void* const* d_in, const int* in_sizes, int n_in,
                              void* d_out, int out_size)
{
    (void)in_sizes; (void)n_in; (void)out_size;
    const float* inputs = (const float*)d_in[0];

    struct LayerP { const float *Wx, *Wh, *b, *g, *be, *mu, *v; };
    LayerP L[4];
    for (int l = 0; l < 4; l++) {
        int base = 1 + 7 * l;
        L[l].Wx = (const float*)d_in[base + 0];
        L[l].Wh = (const float*)d_in[base + 1];
        L[l].b  = (const float*)d_in[base + 2];
        L[l].g  = (const float*)d_in[base + 3];
        L[l].be = (const float*)d_in[base + 4];
        L[l].mu = (const float*)d_in[base + 5];
        L[l].v  = (const float*)d_in[base + 6];
    }
    const float* W3 = (const float*)d_in[29];
    const float* b3 = (const float*)d_in[30];

    float *seqA, *seqB, *hA, *hB, *cbuf, *zx, *Bxh, *Bxl, *Bhh, *Bhl;
    cudaGetSymbolAddress((void**)&seqA, g_seqA);
    cudaGetSymbolAddress((void**)&seqB, g_seqB);
    cudaGetSymbolAddress((void**)&hA,   g_hA);
    cudaGetSymbolAddress((void**)&hB,   g_hB);
    cudaGetSymbolAddress((void**)&cbuf, g_c);
    cudaGetSymbolAddress((void**)&zx,   g_zx);
    cudaGetSymbolAddress((void**)&Bxh,  g_Bxh);
    cudaGetSymbolAddress((void**)&Bxl,  g_Bxl);
    cudaGetSymbolAddress((void**)&Bhh,  g_Bhh);
    cudaGetSymbolAddress((void**)&Bhl,  g_Bhl);

    // smem sizes (bytes)
    const int SM1  = (20 * (128 + 320) + 240) * 4;          // CIN=1  (~36.8 KB)
    const int SM40 = (44 * (128 + 320) + 240) * 4;          // CIN=40 (~80 KB)
    cudaFuncSetAttribute(mma_step<1, 1>,  cudaFuncAttributeMaxDynamicSharedMemorySize, SM1);
    cudaFuncSetAttribute(mma_step<40, 1>, cudaFuncAttributeMaxDynamicSharedMemorySize, SM40);
    cudaFuncSetAttribute(mma_step<40, 0>, cudaFuncAttributeMaxDynamicSharedMemorySize, SM40);

    const int nhc = NB * HH * WW * FF;                      // 1,024,000
    const long long ZBS = (long long)NT * 1600 * 160;       // z buffer per-b stride
    const long long BSO = (long long)NT * 1600 * 40;        // seq buffer per-b stride

    const float* in_seq = inputs;
    float* out_seq = seqA;

    for (int l = 0; l < 4; l++) {
        const int mode = l ? 1 : 0;
        const int nbx  = l ? (9 * 160 * 40) : (160 * 16);
        build_B_kernel<<<(nbx + 255) / 256, 256>>>(L[l].Wx, mode, Bxh, Bxl);
        build_B_kernel<<<(9 * 160 * 40 + 255) / 256, 256>>>(L[l].Wh, 1, Bhh, Bhl);

        // x-conv precompute: M = 512*1600 rows, 64 per CTA
        if (l == 0)
            mma_step<1, 1><<<12800, 128, SM1>>>(in_seq, 1600, Bxh, Bxl, zx,
                nullptr, 0, nullptr, nullptr, nullptr, nullptr, nullptr,
                nullptr, nullptr, nullptr, 0);
        else
            mma_step<40, 1><<<12800, 128, SM40>>>(in_seq, 64000, Bxh, Bxl, zx,
                nullptr, 0, nullptr, nullptr, nullptr, nullptr, nullptr,
                nullptr, nullptr, nullptr, 0);

        zero_kernel<<<(nhc + 255) / 256, 256>>>(hA, nhc);
        zero_kernel<<<(nhc + 255) / 256, 256>>>(cbuf, nhc);
        float* hc = hA;
        float* hn = hB;
        for (int t = 0; t < NT; t++) {
            mma_step<40, 0><<<400, 128, SM40>>>(hc, 64000, Bhh, Bhl, nullptr,
                zx + (size_t)t * 1600 * 160, ZBS,
                L[l].b, L[l].g, L[l].be, L[l].mu, L[l].v,
                hn, cbuf, out_seq + (size_t)t * 1600 * 40, BSO);
            float* tmp = hc; hc = hn; hn = tmp;
        }
        in_seq = out_seq;
        out_seq = (out_seq == seqA) ? seqB : seqA;
    }

    conv3d_kernel<<<dim3(4, HH, NB), dim3(40, 8)>>>(in_seq, W3, b3, (float*)d_out);
}

// round 14
// speedup vs baseline: 3.4512x; 1.8992x over previous
#include <cuda_runtime.h>
#include <cuda_bf16.h>
#include <math.h>
#include <stdint.h>

#define NB 16
#define NT 32
#define HH 40
#define WW 40
#define FF 40

typedef __nv_bfloat16 bf16;

// ---------------- scratch (no allocations allowed) ----------------
__device__ float g_seqA[(size_t)NB*NT*HH*WW*FF];   // 131 MB
__device__ float g_seqB[(size_t)NB*NT*HH*WW*FF];   // 131 MB
__device__ float g_zx [(size_t)NB*NT*HH*WW*160];   // 524 MB  x-conv precompute
__device__ float g_hA[NB*HH*WW*FF];
__device__ float g_hB[NB*HH*WW*FF];
__device__ float g_c [NB*HH*WW*FF];
__device__ bf16 g_Bxh[9*160*48], g_Bxl[9*160*48];  // x-weights packed hi/lo (bf16)
__device__ bf16 g_Bhh[9*160*48], g_Bhl[9*160*48];  // h-weights packed hi/lo

__global__ void zero_kernel(float* __restrict__ p, int n) {
    int i = blockIdx.x * blockDim.x + threadIdx.x;
    if (i < n) p[i] = 0.f;
}

__device__ __forceinline__ float hsig(float x) {
    return fminf(fmaxf(0.2f * x + 0.5f, 0.f), 1.f);
}
// m16n8k16 bf16 mma: d += a * b  (a: 4 regs, b: 2 regs, d: 4 f32)
__device__ __forceinline__ void mma16(float* d, const uint32_t* a, uint32_t b0, uint32_t b1) {
    asm volatile("mma.sync.aligned.m16n8k16.row.col.f32.bf16.bf16.f32 "
        "{%0,%1,%2,%3}, {%4,%5,%6,%7}, {%8,%9}, {%0,%1,%2,%3};"
        : "+f"(d[0]), "+f"(d[1]), "+f"(d[2]), "+f"(d[3])
        : "r"(a[0]), "r"(a[1]), "r"(a[2]), "r"(a[3]), "r"(b0), "r"(b1));
}
__device__ __forceinline__ void split_bf16(float v, bf16& hi, bf16& lo) {
    hi = __float2bfloat16_rn(v);
    lo = __float2bfloat16_rn(v - __bfloat162float(hi));
}

// ---- weight prepass ----
// mode 0 (CIN=1):  out[n][16]    : k<9 -> W[k*160+n], else 0            (160*16)
// mode 1 (CIN=40): out[c][n][48] : j<40 -> W[(c*40+j)*160+n], else 0    (9*160*48)
__global__ void build_B_kernel(const float* __restrict__ W, int mode,
                               bf16* __restrict__ Bh, bf16* __restrict__ Bl)
{
    int idx = blockIdx.x * blockDim.x + threadIdx.x;
    float v = 0.f;
    if (mode == 0) {
        if (idx >= 160 * 16) return;
        int n = idx / 16, k = idx & 15;
        if (k < 9) v = W[k * 160 + n];
    } else {
        if (idx >= 9 * 160 * 48) return;
        int c = idx / 7680, r = idx - c * 7680;
        int n = r / 48, j = r - n * 48;
        if (j < 40) v = W[(size_t)(c * 40 + j) * 160 + n];
    }
    bf16 hi, lo;
    split_bf16(v, hi, lo);
    Bh[idx] = hi;
    Bl[idx] = lo;
}

// ---------------- GEMM step via mma.sync bf16 (3-term hi/lo split) --------
// z[M,160] = im2col(X)[M, K=9*CIN] @ B[160,K]^T
// CTA: 128 threads, 4 warps; warp tile m16 x n160 (20 n-frags, all gates local).
// PRE=1: write z to zpre[p*160].  PRE=0: fused LSTM + BN epilogue.
template<int CIN, int PRE>
__global__ __launch_bounds__(128)
void mma_step(const float* __restrict__ X, long long xbs,
              const bf16* __restrict__ Bh_g, const bf16* __restrict__ Bl_g,
              float* __restrict__ zpre,
              const float* __restrict__ zx_t, long long zbs,
              const float* __restrict__ bias,
              const float* __restrict__ gam, const float* __restrict__ bet,
              const float* __restrict__ mu, const float* __restrict__ var,
              float* __restrict__ h_next, float* __restrict__ c_buf,
              float* __restrict__ out_t, long long bso)
{
    constexpr int CHUNKS = (CIN == 1) ? 1 : 9;
    constexpr int ASTR   = (CIN == 1) ? 24 : 56;   // bf16 row stride (padded)
    constexpr int AS2    = ASTR / 2;               // b32 row stride (12 / 28)
    constexpr int KSTEPS = (CIN == 1) ? 1 : 3;     // k16 steps per chunk

    extern __shared__ char smem[];
    bf16* sAh = (bf16*)smem;
    bf16* sAl = sAh + 64 * ASTR;
    bf16* sBh = sAl + 64 * ASTR;
    bf16* sBl = sBh + 160 * ASTR;
    float* sPar = (float*)(sBl + 160 * ASTR);      // REC: bias[160], scale[40], shift[40]

    const int tid = threadIdx.x;
    const int w   = tid >> 5;
    const int lane = tid & 31;
    const int gid = lane >> 2;      // 0..7
    const int tig = lane & 3;       // 0..3
    const int p0  = blockIdx.x * 64;

    if (!PRE) {
        for (int i = tid; i < 240; i += 128) {
            if (i < 160) sPar[i] = bias[i];
            else if (i < 200) {
                int f = i - 160;
                sPar[i] = gam[f] * rsqrtf(var[f] + 1e-3f);
            } else {
                int f = i - 200;
                sPar[i] = bet[f] - mu[f] * (gam[f] * rsqrtf(var[f] + 1e-3f));
            }
        }
    }
    if (CIN == 40) {
        // zero the k-pad columns (40..47) once; never rewritten by staging
        for (int i = tid; i < 256; i += 128) {
            int row = i >> 2, q = i & 3;
            ((uint32_t*)(sAh + row * ASTR + 40))[q] = 0u;
            ((uint32_t*)(sAl + row * ASTR + 40))[q] = 0u;
        }
    }

    float d[20][4];
#pragma unroll
    for (int j = 0; j < 20; j++)
#pragma unroll
        for (int e = 0; e < 4; e++) d[j][e] = 0.f;

#pragma unroll 1
    for (int c = 0; c < CHUNKS; c++) {
        // ---- stage A (im2col gather + bf16 hi/lo split)
        if (CIN == 1) {
            for (int i = tid; i < 64; i += 128) {
                int p = p0 + i;
                int unit = p / 1600, pp = p - unit * 1600;
                int pr = pp / 40, pw = pp - pr * 40;
                bf16* ph = sAh + i * ASTR;
                bf16* pl = sAl + i * ASTR;
#pragma unroll
                for (int k = 0; k < 16; k += 2) {
                    float v0 = 0.f, v1 = 0.f;
                    if (k < 9) {
                        int rr = pr + k / 3 - 1, cc = pw + k % 3 - 1;
                        if ((unsigned)rr < 40u && (unsigned)cc < 40u)
                            v0 = X[(size_t)unit * xbs + rr * 40 + cc];
                    }
                    if (k + 1 < 9) {
                        int k1 = k + 1;
                        int rr = pr + k1 / 3 - 1, cc = pw + k1 % 3 - 1;
                        if ((unsigned)rr < 40u && (unsigned)cc < 40u)
                            v1 = X[(size_t)unit * xbs + rr * 40 + cc];
                    }
                    __nv_bfloat162 h2, l2;
                    split_bf16(v0, h2.x, l2.x);
                    split_bf16(v1, h2.y, l2.y);
                    *(__nv_bfloat162*)(ph + k) = h2;
                    *(__nv_bfloat162*)(pl + k) = l2;
                }
            }
            for (int i = tid; i < 320; i += 128) {
                int n = i >> 1, g = i & 1;
                *(float4*)(sBh + n * ASTR + g * 8) = *(const float4*)(Bh_g + n * 16 + g * 8);
                *(float4*)(sBl + n * ASTR + g * 8) = *(const float4*)(Bl_g + n * 16 + g * 8);
            }
        } else {
            const int dyy = c / 3 - 1, dxx = c % 3 - 1;
            for (int i = tid; i < 640; i += 128) {
                int row = i / 10, g = i - row * 10;
                int p = p0 + row;
                int unit = p / 1600, pp = p - unit * 1600;
                int pr = pp / 40, pw = pp - pr * 40;
                int rr = pr + dyy, cc = pw + dxx;
                float4 v = make_float4(0.f, 0.f, 0.f, 0.f);
                if ((unsigned)rr < 40u && (unsigned)cc < 40u)
                    v = *(const float4*)(X + (size_t)unit * xbs
                                         + (size_t)(rr * 40 + cc) * 40 + g * 4);
                __nv_bfloat162 h0, h1, l0, l1;
                split_bf16(v.x, h0.x, l0.x);
                split_bf16(v.y, h0.y, l0.y);
                split_bf16(v.z, h1.x, l1.x);
                split_bf16(v.w, h1.y, l1.y);
                __nv_bfloat162* ph = (__nv_bfloat162*)(sAh + row * ASTR + g * 4);
                __nv_bfloat162* pl = (__nv_bfloat162*)(sAl + row * ASTR + g * 4);
                ph[0] = h0; ph[1] = h1;
                pl[0] = l0; pl[1] = l1;
            }
            for (int i = tid; i < 960; i += 128) {
                int n = i / 6, g = i - n * 6;
                size_t src = (size_t)(c * 160 + n) * 48 + g * 8;
                *(float4*)(sBh + n * ASTR + g * 8) = *(const float4*)(Bh_g + src);
                *(float4*)(sBl + n * ASTR + g * 8) = *(const float4*)(Bl_g + src);
            }
        }
        __syncthreads();

        // ---- mma over this chunk
        const uint32_t* Ah32 = (const uint32_t*)sAh;
        const uint32_t* Al32 = (const uint32_t*)sAl;
        const uint32_t* Bh32 = (const uint32_t*)sBh;
        const uint32_t* Bl32 = (const uint32_t*)sBl;
#pragma unroll
        for (int ks = 0; ks < KSTEPS; ks++) {
            uint32_t ah[4], al[4];
            {
                int ra = (w * 16 + gid) * AS2 + ks * 8 + tig;
                ah[0] = Ah32[ra];      ah[1] = Ah32[ra + 8 * AS2];
                ah[2] = Ah32[ra + 4];  ah[3] = Ah32[ra + 8 * AS2 + 4];
                al[0] = Al32[ra];      al[1] = Al32[ra + 8 * AS2];
                al[2] = Al32[ra + 4];  al[3] = Al32[ra + 8 * AS2 + 4];
            }
#pragma unroll
            for (int j = 0; j < 20; j++) {
                int rb = (8 * j + gid) * AS2 + ks * 8 + tig;
                uint32_t bh0 = Bh32[rb], bh1 = Bh32[rb + 4];
                uint32_t bl0 = Bl32[rb], bl1 = Bl32[rb + 4];
                mma16(d[j], ah, bh0, bh1);
                mma16(d[j], ah, bl0, bl1);
                mma16(d[j], al, bh0, bh1);
            }
        }
        __syncthreads();
    }

    // ---------------- epilogue ----------------
    // Thread holds rows (w*16+gid, +8), cols {8j'+2tig, +1} in each gate block.
#pragma unroll
    for (int half = 0; half < 2; half++) {
        const int r = w * 16 + gid + 8 * half;
        const int p = p0 + r;
        if (PRE) {
            float* zp = zpre + (size_t)p * 160;
#pragma unroll
            for (int g = 0; g < 4; g++)
#pragma unroll
                for (int j = 0; j < 5; j++) {
                    int n = g * 40 + 8 * j + 2 * tig;
                    float2 v = make_float2(d[g * 5 + j][half * 2],
                                           d[g * 5 + j][half * 2 + 1]);
                    *(float2*)(zp + n) = v;
                }
        } else {
            const int b = p / 1600, pp = p - b * 1600;
            const float* zr = zx_t + (size_t)b * zbs + (size_t)pp * 160;
            float* cb = c_buf  + (size_t)p * 40;
            float* hb = h_next + (size_t)p * 40;
            float* ob = out_t  + (size_t)b * bso + (size_t)pp * 40;
#pragma unroll
            for (int j = 0; j < 5; j++) {
                const int ch = 8 * j + 2 * tig;
                float2 xi = *(const float2*)(zr + ch);
                float2 xf = *(const float2*)(zr + 40 + ch);
                float2 xg = *(const float2*)(zr + 80 + ch);
                float2 xo = *(const float2*)(zr + 120 + ch);
                float2 cc = *(const float2*)(cb + ch);
                float2 cn, hn, on;
#pragma unroll
                for (int e = 0; e < 2; e++) {
                    int n = ch + e;
                    int di = half * 2 + e;
                    float zi = (e ? xi.y : xi.x) + d[0 * 5 + j][di] + sPar[n];
                    float zf = (e ? xf.y : xf.x) + d[1 * 5 + j][di] + sPar[40 + n];
                    float zg = (e ? xg.y : xg.x) + d[2 * 5 + j][di] + sPar[80 + n];
                    float zo = (e ? xo.y : xo.x) + d[3 * 5 + j][di] + sPar[120 + n];
                    float cold = e ? cc.y : cc.x;
                    float cq = hsig(zf) * cold + hsig(zi) * tanhf(zg);
                    float hq = hsig(zo) * tanhf(cq);
                    float oq = hq * sPar[160 + n] + sPar[200 + n];
                    if (e) { cn.y = cq; hn.y = hq; on.y = oq; }
                    else   { cn.x = cq; hn.x = hq; on.x = oq; }
                }
                *(float2*)(cb + ch) = cn;
                *(float2*)(hb + ch) = hn;
                *(float2*)(ob + ch) = on;
            }
        }
    }
}

// ---------------- final Conv3D (3x3x3 over T,H,W) + sigmoid ----------------
__global__ __launch_bounds__(320)
void conv3d_kernel(const float* __restrict__ in,    // [B][T][H][W][FF]
                   const float* __restrict__ W3,    // [3][3][3][FF]
                   const float* __restrict__ b3,
                   float* __restrict__ out)         // [B][T][H][W]
{
    __shared__ __align__(16) float ws[27 * FF];
    int tid = threadIdx.y * 40 + threadIdx.x;
    for (int i = tid; i < 27 * FF; i += 320) ws[i] = W3[i];
    __syncthreads();

    const int w   = threadIdx.x;
    const int t   = blockIdx.x * 8 + threadIdx.y;
    const int row = blockIdx.y;
    const int b   = blockIdx.z;

    float acc = b3[0];
#pragma unroll
    for (int dt = 0; dt < 3; dt++) {
        int tt = t + dt - 1;
        if ((unsigned)tt >= NT) continue;
#pragma unroll
        for (int dh = 0; dh < 3; dh++) {
            int rr = row + dh - 1;
            if ((unsigned)rr >= HH) continue;
            const float* rp = in + ((size_t)(b * NT + tt) * HH + rr) * WW * FF;
#pragma unroll
            for (int dw = 0; dw < 3; dw++) {
                int cc = w + dw - 1;
                if ((unsigned)cc >= WW) continue;
                const float4* pp = (const float4*)(rp + (size_t)cc * FF);
                const float*  wp = ws + ((dt * 3 + dh) * 3 + dw) * FF;
#pragma unroll
                for (int q = 0; q < 10; q++) {
                    float4 v  = pp[q];
                    float4 wv = *(const float4*)(wp + q * 4);
                    acc += v.x * wv.x + v.y * wv.y + v.z * wv.z + v.w * wv.w;
                }
            }
        }
    }
    out[((size_t)(b * NT + t) * HH + row) * WW + w] = 1.f / (1.f + expf(-acc));
}

// ---------------- launch ----------------
extern "C" void kernel_launch(void* const* d_in, const int* in_sizes, int n_in,
                              void* d_out, int out_size)
{
    (void)in_sizes; (void)n_in; (void)out_size;
    const float* inputs = (const float*)d_in[0];

    struct LayerP { const float *Wx, *Wh, *b, *g, *be, *mu, *v; };
    LayerP L[4];
    for (int l = 0; l < 4; l++) {
        int base = 1 + 7 * l;
        L[l].Wx = (const float*)d_in[base + 0];
        L[l].Wh = (const float*)d_in[base + 1];
        L[l].b  = (const float*)d_in[base + 2];
        L[l].g  = (const float*)d_in[base + 3];
        L[l].be = (const float*)d_in[base + 4];
        L[l].mu = (const float*)d_in[base + 5];
        L[l].v  = (const float*)d_in[base + 6];
    }
    const float* W3 = (const float*)d_in[29];
    const float* b3 = (const float*)d_in[30];

    float *seqA, *seqB, *hA, *hB, *cbuf, *zx;
    bf16 *Bxh, *Bxl, *Bhh, *Bhl;
    cudaGetSymbolAddress((void**)&seqA, g_seqA);
    cudaGetSymbolAddress((void**)&seqB, g_seqB);
    cudaGetSymbolAddress((void**)&hA,   g_hA);
    cudaGetSymbolAddress((void**)&hB,   g_hB);
    cudaGetSymbolAddress((void**)&cbuf, g_c);
    cudaGetSymbolAddress((void**)&zx,   g_zx);
    cudaGetSymbolAddress((void**)&Bxh,  g_Bxh);
    cudaGetSymbolAddress((void**)&Bxl,  g_Bxl);
    cudaGetSymbolAddress((void**)&Bhh,  g_Bhh);
    cudaGetSymbolAddress((void**)&Bhl,  g_Bhl);

    // smem sizes (bytes): bf16 tiles + 240-float params
    const int SM1  = (64 * 24 * 2 + 160 * 24 * 2) * 2 + 240 * 4;   // 22464
    const int SM40 = (64 * 56 * 2 + 160 * 56 * 2) * 2 + 240 * 4;   // 51136
    cudaFuncSetAttribute(mma_step<1, 1>,  cudaFuncAttributeMaxDynamicSharedMemorySize, SM1);
    cudaFuncSetAttribute(mma_step<40, 1>, cudaFuncAttributeMaxDynamicSharedMemorySize, SM40);
    cudaFuncSetAttribute(mma_step<40, 0>, cudaFuncAttributeMaxDynamicSharedMemorySize, SM40);

    const int nhc = NB * HH * WW * FF;                      // 1,024,000
    const long long ZBS = (long long)NT * 1600 * 160;       // z buffer per-b stride
    const long long BSO = (long long)NT * 1600 * 40;        // seq buffer per-b stride

    const float* in_seq = inputs;
    float* out_seq = seqA;

    for (int l = 0; l < 4; l++) {
        const int mode = l ? 1 : 0;
        const int nbx  = l ? (9 * 160 * 48) : (160 * 16);
        build_B_kernel<<<(nbx + 255) / 256, 256>>>(L[l].Wx, mode, Bxh, Bxl);
        build_B_kernel<<<(9 * 160 * 48 + 255) / 256, 256>>>(L[l].Wh, 1, Bhh, Bhl);

        // x-conv precompute: M = 512*1600 rows, 64 per CTA
        if (l == 0)
            mma_step<1, 1><<<12800, 128, SM1>>>(in_seq, 1600, Bxh, Bxl, zx,
                nullptr, 0, nullptr, nullptr, nullptr, nullptr, nullptr,
                nullptr, nullptr, nullptr, 0);
        else
            mma_step<40, 1><<<12800, 128, SM40>>>(in_seq, 64000, Bxh, Bxl, zx,
                nullptr, 0, nullptr, nullptr, nullptr, nullptr, nullptr,
                nullptr, nullptr, nullptr, 0);

        zero_kernel<<<(nhc + 255) / 256, 256>>>(hA, nhc);
        zero_kernel<<<(nhc + 255) / 256, 256>>>(cbuf, nhc);
        float* hc = hA;
        float* hn = hB;
        for (int t = 0; t < NT; t++) {
            mma_step<40, 0><<<400, 128, SM40>>>(hc, 64000, Bhh, Bhl, nullptr,
                zx + (size_t)t * 1600 * 160, ZBS,
                L[l].b, L[l].g, L[l].be, L[l].mu, L[l].v,
                hn, cbuf, out_seq + (size_t)t * 1600 * 40, BSO);
            float* tmp = hc; hc = hn; hn = tmp;
        }
        in_seq = out_seq;
        out_seq = (out_seq == seqA) ? seqB : seqA;
    }

    conv3d_kernel<<<dim3(4, HH, NB), dim3(40, 8)>>>(in_seq, W3, b3, (float*)d_out);
}